// round 1
// baseline (speedup 1.0000x reference)
#include <cuda_runtime.h>
#include <math.h>

#define Bsz 8
#define Sq 2048
#define Dd 256
#define Hh 8

#define BM 64
#define BN 32
#define QSP 68   // Qs row stride (floats): mult of 4 for LDS.128 alignment
#define KSP 34   // Ks row stride: mult of 2 for LDS.64 alignment
#define PSP 33   // Ps row stride: conflict-free row sums

// Scratch (no cudaMalloc allowed): folded projection matrix + pre-projected E
__device__ float g_weff[Dd * Dd];
__device__ float g_e2[(size_t)Bsz * Sq * Dd];

// ---------------------------------------------------------------------------
// Kernel 1: W_eff[d][dp] = sum_h W_o[d][h*256 + dp]
// ---------------------------------------------------------------------------
__global__ void weff_kernel(const float* __restrict__ Wo) {
    int d  = blockIdx.x;
    int dp = threadIdx.x;
    float s = 0.f;
#pragma unroll
    for (int h = 0; h < Hh; h++)
        s += Wo[(size_t)d * (Dd * Hh) + h * Dd + dp];
    g_weff[d * Dd + dp] = s;
}

// ---------------------------------------------------------------------------
// Kernel 2: e2[m][n] = sum_k e[m][k] * W_eff[n][k]   (M=16384, N=256, K=256)
// 64x64 tile, BK=32, 256 threads, 4x4 microtile.
// ---------------------------------------------------------------------------
__global__ void e2_gemm_kernel(const float* __restrict__ E) {
    __shared__ float As[32][68];   // [k][m], padded
    __shared__ float Bs[32][68];   // [k][n], padded
    int tid = threadIdx.x;
    int m0 = blockIdx.x * 64;
    int n0 = blockIdx.y * 64;
    int ty = tid >> 4, tx = tid & 15;
    int lr = tid >> 5;      // 0..7
    int lc = tid & 31;      // 0..31

    float acc[4][4];
#pragma unroll
    for (int i = 0; i < 4; i++)
#pragma unroll
        for (int j = 0; j < 4; j++) acc[i][j] = 0.f;

    for (int k0 = 0; k0 < Dd; k0 += 32) {
#pragma unroll
        for (int i = 0; i < 8; i++) {
            int row = lr + i * 8;
            As[lc][row] = E[(size_t)(m0 + row) * Dd + k0 + lc];
            Bs[lc][row] = g_weff[(size_t)(n0 + row) * Dd + k0 + lc];
        }
        __syncthreads();
#pragma unroll
        for (int kk = 0; kk < 32; kk++) {
            float4 a = *(const float4*)&As[kk][ty * 4];
            float4 b = *(const float4*)&Bs[kk][tx * 4];
            float av[4] = {a.x, a.y, a.z, a.w};
            float bv[4] = {b.x, b.y, b.z, b.w};
#pragma unroll
            for (int i = 0; i < 4; i++)
#pragma unroll
                for (int j = 0; j < 4; j++) acc[i][j] += av[i] * bv[j];
        }
        __syncthreads();
    }
#pragma unroll
    for (int i = 0; i < 4; i++) {
        float4 v = make_float4(acc[i][0], acc[i][1], acc[i][2], acc[i][3]);
        *(float4*)&g_e2[(size_t)(m0 + ty * 4 + i) * Dd + n0 + tx * 4] = v;
    }
}

// ---------------------------------------------------------------------------
// Kernel 3: causal attention with clipped scores (no softmax max needed).
// One CTA = 64 q-rows of one batch. Streams 32-wide k-tiles.
//   out[b][q][c] = (1/(q+1)) * (1/denom[q]) * sum_k exp(clip(q.k/16)) * e2[b][k][c]
// ---------------------------------------------------------------------------
__global__ void attn_kernel(const float* __restrict__ P, float* __restrict__ Out) {
    extern __shared__ float sm[];
    float* Qs = sm;                      // [256][QSP]  d-major
    float* Ks = Qs + 256 * QSP;          // [256][KSP]  d-major
    float* Es = Ks + 256 * KSP;          // [32][256]   k-major
    float* Ps = Es + 32 * 256;           // [64][PSP]   probabilities
    float* Dn = Ps + 64 * PSP;           // [64]        denominators

    int g = blockIdx.x;                       // 0..255, heaviest diagonals first
    int m = (gridDim.x / Bsz - 1) - (g >> 3); // q-tile index, descending
    int b = g & (Bsz - 1);
    int tid = threadIdx.x;
    int q0 = m * BM;
    const float* pb = P + (size_t)b * (Sq + 1) * Dd;

    // Load Q tile (rows q0..q0+63, p shifted by +1) transposed to d-major.
#pragma unroll 4
    for (int r = 0; r < BM; r++)
        Qs[tid * QSP + r] = pb[(size_t)(q0 + r + 1) * Dd + tid];
    if (tid < BM) Dn[tid] = 0.f;

    float acc[64];
#pragma unroll
    for (int i = 0; i < 64; i++) acc[i] = 0.f;

    int w = tid >> 5, lane = tid & 31;   // phase B mapping: warp w -> rows w*8..+7
    int ty = tid >> 4, tx = tid & 15;    // phase A mapping: 4x2 microtile

    int kend = q0 + BM;
    for (int kb = 0; kb < kend; kb += BN) {
        __syncthreads();
        // Load K tile transposed to d-major, E2 tile k-major.
#pragma unroll 4
        for (int kr = 0; kr < BN; kr++)
            Ks[tid * KSP + kr] = pb[(size_t)(kb + kr) * Dd + tid];
        const float* e2b = g_e2 + ((size_t)b * Sq + kb) * Dd;
#pragma unroll 4
        for (int kr = 0; kr < BN; kr++)
            Es[kr * 256 + tid] = e2b[kr * Dd + tid];
        __syncthreads();

        // Phase A: S[64][32] = Q . K^T  (4x2 per thread, vectorized smem reads)
        float s[4][2];
#pragma unroll
        for (int i = 0; i < 4; i++) { s[i][0] = 0.f; s[i][1] = 0.f; }
#pragma unroll 8
        for (int d = 0; d < 256; d++) {
            float4 q = *(const float4*)&Qs[d * QSP + ty * 4];
            float2 k = *(const float2*)&Ks[d * KSP + tx * 2];
            s[0][0] += q.x * k.x; s[0][1] += q.x * k.y;
            s[1][0] += q.y * k.x; s[1][1] += q.y * k.y;
            s[2][0] += q.z * k.x; s[2][1] += q.z * k.y;
            s[3][0] += q.w * k.x; s[3][1] += q.w * k.y;
        }
        // scale, clip, causal mask, exp -> Ps
#pragma unroll
        for (int i = 0; i < 4; i++)
#pragma unroll
            for (int j = 0; j < 2; j++) {
                int qr = q0 + ty * 4 + i;
                int kc = kb + tx * 2 + j;
                float v = s[i][j] * 0.0625f;
                v = fminf(fmaxf(v, -10.f), 10.f);
                Ps[(ty * 4 + i) * PSP + tx * 2 + j] = (kc <= qr) ? __expf(v) : 0.f;
            }
        __syncthreads();

        // Row denominators (2 warps; overlaps with phase B of other warps)
        if (tid < BM) {
            float sum = 0.f;
#pragma unroll
            for (int kk = 0; kk < BN; kk++) sum += Ps[tid * PSP + kk];
            Dn[tid] += sum;
        }

        // Phase B: acc[64][256] += P[64][32] . E2[32][256]
#pragma unroll 2
        for (int kk = 0; kk < BN; kk++) {
            float pv[8];
#pragma unroll
            for (int i = 0; i < 8; i++) pv[i] = Ps[(w * 8 + i) * PSP + kk];
#pragma unroll
            for (int u = 0; u < 8; u++) {
                float ev = Es[kk * 256 + lane + 32 * u];
#pragma unroll
                for (int i = 0; i < 8; i++) acc[i * 8 + u] += pv[i] * ev;
            }
        }
    }
    __syncthreads();

    // Epilogue: divide by denom, apply 1/(q+1) row scale, store.
    float* ob = Out + ((size_t)b * Sq + q0) * Dd;
#pragma unroll
    for (int i = 0; i < 8; i++) {
        int r = w * 8 + i;
        float scale = 1.f / ((float)(q0 + r + 1) * Dn[r]);
#pragma unroll
        for (int u = 0; u < 8; u++)
            ob[(size_t)r * Dd + lane + 32 * u] = acc[i * 8 + u] * scale;
    }
}

// ---------------------------------------------------------------------------
extern "C" void kernel_launch(void* const* d_in, const int* in_sizes, int n_in,
                              void* d_out, int out_size) {
    const float* e  = (const float*)d_in[0];
    const float* p  = (const float*)d_in[1];
    const float* Wo = (const float*)d_in[2];
    float* out = (float*)d_out;

    size_t smem = (size_t)(256 * QSP + 256 * KSP + 32 * 256 + 64 * PSP + 64) * sizeof(float);
    cudaFuncSetAttribute(attn_kernel, cudaFuncAttributeMaxDynamicSharedMemorySize, (int)smem);

    weff_kernel<<<Dd, Dd>>>(Wo);
    e2_gemm_kernel<<<dim3((Bsz * Sq) / 64, Dd / 64), 256>>>(e);
    attn_kernel<<<Bsz * (Sq / BM), 256, smem>>>(p, out);
}